// round 1
// baseline (speedup 1.0000x reference)
#include <cuda_runtime.h>
#include <cstdint>

// Problem constants
#define B_  16
#define N_  8192
#define C_  256
#define K_  4096

// Output layout (float32): [features (B*K*C)] [indices (B*K)] [adjacency (B*K*K)] [scores (B*K)]
#define OFF_FEAT   ((size_t)0)
#define OFF_IDX    ((size_t)B_ * K_ * C_)                 // 16,777,216
#define OFF_ADJ    (OFF_IDX + (size_t)B_ * K_)            // 16,842,752
#define OFF_SCORES (OFF_ADJ + (size_t)B_ * K_ * K_)       // 285,278,208

// Scratch (device globals; no allocation allowed)
__device__ __align__(16) unsigned short g_idx[B_ * K_];   // top-k indices per batch (descending score order)
__device__ int g_pos[B_ * N_];                            // pos[b][r] = rank i if r selected in batch b, else -1

// ---------------------------------------------------------------------------
// Kernel 1: per-batch stable descending sort of (score, index), take top 4096.
// One CTA per batch, bitonic sort in static shared memory (48KB exactly).
// Comparator: descending by order-flipped float bits, ties broken by lower
// original index first (matches jax.lax.top_k).
// ---------------------------------------------------------------------------
__global__ __launch_bounds__(1024, 1)
void topk_kernel(const float* __restrict__ scores,
                 float* __restrict__ out_idxf,
                 float* __restrict__ out_scores)
{
    __shared__ unsigned int   sk[N_];   // 32 KB
    __shared__ unsigned short si[N_];   // 16 KB
    const int b = blockIdx.x;
    const float* s = scores + (size_t)b * N_;

    for (int t = threadIdx.x; t < N_; t += blockDim.x) {
        unsigned u = __float_as_uint(s[t]);
        u ^= (u & 0x80000000u) ? 0xFFFFFFFFu : 0x80000000u;  // order-preserving flip
        sk[t] = u;
        si[t] = (unsigned short)t;
        g_pos[b * N_ + t] = -1;
    }
    __syncthreads();

    // Bitonic sort, descending (ties: ascending index)
    for (int k = 2; k <= N_; k <<= 1) {
        for (int j = k >> 1; j > 0; j >>= 1) {
            for (int t = threadIdx.x; t < N_; t += blockDim.x) {
                int ixj = t ^ j;
                if (ixj > t) {
                    bool up = ((t & k) != 0);             // inverted => descending overall
                    unsigned a = sk[t], c = sk[ixj];
                    unsigned short ia = si[t], ic = si[ixj];
                    bool before = (a > c) || (a == c && ia < ic);
                    if (before == up) {
                        sk[t] = c; sk[ixj] = a;
                        si[t] = ic; si[ixj] = ia;
                    }
                }
            }
            __syncthreads();
        }
    }

    // Emit top-K: indices (as float), scores (re-gathered, exact), scratch maps
    for (int t = threadIdx.x; t < K_; t += blockDim.x) {
        int idx = si[t];
        g_idx[b * K_ + t] = (unsigned short)idx;
        out_idxf[(size_t)b * K_ + t]   = (float)idx;
        out_scores[(size_t)b * K_ + t] = s[idx];
        g_pos[b * N_ + idx] = t;
    }
}

// ---------------------------------------------------------------------------
// Kernel 2: gather selected features. out[b][i][:] = features[b][idx[b][i]][:]
// float4 throughout, fully coalesced. One float4 per thread.
// ---------------------------------------------------------------------------
__global__ __launch_bounds__(256)
void feat_kernel(const float4* __restrict__ feat, float4* __restrict__ out)
{
    int o = blockIdx.x * blockDim.x + threadIdx.x;    // 0 .. B*K*C/4 - 1
    int row = o >> 6;                                  // C/4 = 64 float4 per row
    int c   = o & 63;
    int b   = row >> 12;                               // K = 4096 rows per batch
    int r   = g_idx[row];
    out[o] = feat[((size_t)(b << 13) + r) * 64 + c];   // N = 8192 rows per batch in src
}

// ---------------------------------------------------------------------------
// Kernel 3: adjacency gather with source-row reuse.
// One CTA per source row r: load A[r][:] (32KB) into SMEM once, then for each
// batch b with pos[b][r] = i >= 0, write out[b][i][j] = smem[idx[b][j]] for all j.
// Index reads are ushort4 (8B/thread), writes are float4 (coalesced).
// ---------------------------------------------------------------------------
__global__ __launch_bounds__(512)
void adj_kernel(const float* __restrict__ A, float* __restrict__ out)
{
    __shared__ float row[N_];   // 32 KB
    const int r = blockIdx.x;

    const float4* src  = (const float4*)(A + (size_t)r * N_);
    float4*       rowv = (float4*)row;
    for (int t = threadIdx.x; t < N_ / 4; t += blockDim.x)
        rowv[t] = src[t];
    __syncthreads();

    #pragma unroll 1
    for (int b = 0; b < B_; ++b) {
        int i = g_pos[b * N_ + r];
        if (i < 0) continue;
        float4* obase = (float4*)(out + ((size_t)b * K_ + i) * K_);
        const ushort4* idx4 = (const ushort4*)(g_idx + b * K_);
        for (int t = threadIdx.x; t < K_ / 4; t += blockDim.x) {
            ushort4 c = idx4[t];
            obase[t] = make_float4(row[c.x], row[c.y], row[c.z], row[c.w]);
        }
    }
}

// ---------------------------------------------------------------------------
extern "C" void kernel_launch(void* const* d_in, const int* in_sizes, int n_in,
                              void* d_out, int out_size)
{
    const float* scores = (const float*)d_in[0];   // (B, N)
    const float* feat   = (const float*)d_in[1];   // (B, N, C)
    const float* adj    = (const float*)d_in[2];   // (N, N)
    float* out = (float*)d_out;

    float* out_feat   = out + OFF_FEAT;
    float* out_idxf   = out + OFF_IDX;
    float* out_adj    = out + OFF_ADJ;
    float* out_scores = out + OFF_SCORES;

    topk_kernel<<<B_, 1024>>>(scores, out_idxf, out_scores);

    int n_f4 = (B_ * K_ * C_) / 4;                 // 4,194,304
    feat_kernel<<<n_f4 / 256, 256>>>((const float4*)feat, (float4*)out_feat);

    adj_kernel<<<N_, 512>>>(adj, out_adj);
}

// round 2
// speedup vs baseline: 1.1163x; 1.1163x over previous
#include <cuda_runtime.h>
#include <cstdint>

// Problem constants
#define B_  16
#define N_  8192
#define C_  256
#define K_  4096

// Output layout (float32): [features (B*K*C)] [indices (B*K)] [adjacency (B*K*K)] [scores (B*K)]
#define OFF_FEAT   ((size_t)0)
#define OFF_IDX    ((size_t)B_ * K_ * C_)
#define OFF_ADJ    (OFF_IDX + (size_t)B_ * K_)
#define OFF_SCORES (OFF_ADJ + (size_t)B_ * K_ * K_)

// Scratch (device globals; no allocation allowed)
__device__ __align__(16) unsigned short g_idx[B_ * K_];   // top-k indices per batch
__device__ int g_pos[B_ * N_];                            // pos[b][r] = rank i, else -1

// ---------------------------------------------------------------------------
// Kernel 1: per-batch stable descending top-k via bitonic sort on u64
// composite keys (flipped_float << 16 | (8191 - idx)).  Descending composite
// == descending score, ties broken by ascending index (matches jax.lax.top_k).
// Stages with j<=16 are fused in registers via shfl_xor (32-elem windows);
// stages with j>=32 run in shared memory with a half-work pair mapping.
// ---------------------------------------------------------------------------
__device__ __forceinline__ unsigned long long bitonic_shfl_step(
    unsigned long long v, int j, bool keepmax)
{
    unsigned long long o = __shfl_xor_sync(0xFFFFFFFFu, v, j);
    unsigned long long mx = v > o ? v : o;
    unsigned long long mn = v > o ? o : v;
    return keepmax ? mx : mn;
}

__global__ __launch_bounds__(1024, 1)
void topk_kernel(const float* __restrict__ scores,
                 float* __restrict__ out_idxf,
                 float* __restrict__ out_scores)
{
    extern __shared__ unsigned long long s[];   // N_ * 8 = 64 KB dynamic
    const int b = blockIdx.x;
    const float* sc = scores + (size_t)b * N_;
    const int tid = threadIdx.x;

    // Load + build composites, clear pos map
    for (int t = tid; t < N_; t += 1024) {
        unsigned u = __float_as_uint(sc[t]);
        u ^= (u & 0x80000000u) ? 0xFFFFFFFFu : 0x80000000u;   // order-preserving flip
        s[t] = ((unsigned long long)u << 16) | (unsigned)(8191 - t);
        g_pos[b * N_ + t] = -1;
    }
    __syncthreads();

    // --- Fused register pass: all stages for k = 2,4,8,16,32 (j <= 16) ---
    #pragma unroll 1
    for (int q = 0; q < N_ / 1024; ++q) {
        int i = q * 1024 + tid;                 // lane = i & 31
        unsigned long long v = s[i];
        #pragma unroll
        for (int k = 2; k <= 32; k <<= 1) {
            #pragma unroll
            for (int j = k >> 1; j > 0; j >>= 1) {
                bool keepmax = (((i & k) == 0) == ((i & j) == 0));
                v = bitonic_shfl_step(v, j, keepmax);
            }
        }
        s[i] = v;
    }
    __syncthreads();

    // --- Main passes k = 64 .. 8192 ---
    #pragma unroll 1
    for (int k = 64; k <= N_; k <<= 1) {
        // large-j stages in shared memory
        #pragma unroll 1
        for (int j = k >> 1; j >= 32; j >>= 1) {
            #pragma unroll
            for (int q = 0; q < 4; ++q) {
                int p = tid + q * 1024;                         // 0..4095
                int i = ((p & ~(j - 1)) << 1) | (p & (j - 1));  // pair base
                int m = i + j;
                bool desc = (i & k) == 0;
                unsigned long long a = s[i], c = s[m];
                if ((a < c) == desc) { s[i] = c; s[m] = a; }
            }
            __syncthreads();
        }
        // fused register tail: j = 16..1
        #pragma unroll 1
        for (int q = 0; q < N_ / 1024; ++q) {
            int i = q * 1024 + tid;
            unsigned long long v = s[i];
            bool desc = (i & k) == 0;
            #pragma unroll
            for (int j = 16; j > 0; j >>= 1) {
                bool keepmax = (desc == ((i & j) == 0));
                v = bitonic_shfl_step(v, j, keepmax);
            }
            s[i] = v;
        }
        __syncthreads();
    }

    // Emit top-K: indices (as float), scores (decoded from key), scratch maps
    for (int t = tid; t < K_; t += 1024) {
        unsigned long long v = s[t];
        int idx = 8191 - (int)(v & 0xFFFF);
        unsigned ku = (unsigned)(v >> 16);
        unsigned orig = (ku & 0x80000000u) ? (ku ^ 0x80000000u) : ~ku;  // inverse flip
        g_idx[b * K_ + t] = (unsigned short)idx;
        out_idxf[(size_t)b * K_ + t]   = (float)idx;
        out_scores[(size_t)b * K_ + t] = __uint_as_float(orig);
        g_pos[b * N_ + idx] = t;
    }
}

// ---------------------------------------------------------------------------
// Kernel 2: gather selected features. out[b][i][:] = features[b][idx[b][i]][:]
// ---------------------------------------------------------------------------
__global__ __launch_bounds__(256)
void feat_kernel(const float4* __restrict__ feat, float4* __restrict__ out)
{
    int o = blockIdx.x * blockDim.x + threadIdx.x;    // 0 .. B*K*C/4 - 1
    int row = o >> 6;                                  // C/4 = 64 float4 per row
    int c   = o & 63;
    int b   = row >> 12;                               // K = 4096 rows per batch
    int r   = g_idx[row];
    out[o] = feat[((size_t)(b << 13) + r) * 64 + c];   // N = 8192 rows per batch
}

// ---------------------------------------------------------------------------
// Kernel 3: adjacency gather with source-row reuse.
// One CTA per source row r: stage A[r][:] (32KB) in SMEM once, serve every
// batch whose top-k contains r (avg 8 of 16).
// ---------------------------------------------------------------------------
__global__ __launch_bounds__(512)
void adj_kernel(const float* __restrict__ A, float* __restrict__ out)
{
    __shared__ float row[N_];   // 32 KB
    const int r = blockIdx.x;

    const float4* src  = (const float4*)(A + (size_t)r * N_);
    float4*       rowv = (float4*)row;
    for (int t = threadIdx.x; t < N_ / 4; t += blockDim.x)
        rowv[t] = src[t];
    __syncthreads();

    #pragma unroll 1
    for (int b = 0; b < B_; ++b) {
        int i = g_pos[b * N_ + r];
        if (i < 0) continue;
        float4* obase = (float4*)(out + ((size_t)b * K_ + i) * K_);
        const ushort4* idx4 = (const ushort4*)(g_idx + b * K_);
        for (int t = threadIdx.x; t < K_ / 4; t += blockDim.x) {
            ushort4 c = idx4[t];
            obase[t] = make_float4(row[c.x], row[c.y], row[c.z], row[c.w]);
        }
    }
}

// ---------------------------------------------------------------------------
extern "C" void kernel_launch(void* const* d_in, const int* in_sizes, int n_in,
                              void* d_out, int out_size)
{
    const float* scores = (const float*)d_in[0];   // (B, N)
    const float* feat   = (const float*)d_in[1];   // (B, N, C)
    const float* adj    = (const float*)d_in[2];   // (N, N)
    float* out = (float*)d_out;

    float* out_feat   = out + OFF_FEAT;
    float* out_idxf   = out + OFF_IDX;
    float* out_adj    = out + OFF_ADJ;
    float* out_scores = out + OFF_SCORES;

    static bool attr_set = false;
    if (!attr_set) {
        cudaFuncSetAttribute(topk_kernel,
                             cudaFuncAttributeMaxDynamicSharedMemorySize,
                             N_ * sizeof(unsigned long long));
        attr_set = true;
    }

    topk_kernel<<<B_, 1024, N_ * sizeof(unsigned long long)>>>(scores, out_idxf, out_scores);

    int n_f4 = (B_ * K_ * C_) / 4;
    feat_kernel<<<n_f4 / 256, 256>>>((const float4*)feat, (float4*)out_feat);

    adj_kernel<<<N_, 512>>>(adj, out_adj);
}